// round 1
// baseline (speedup 1.0000x reference)
#include <cuda_runtime.h>
#include <cstdint>

#define BATCH 64
#define NPTS  1024
#define H16   256
#define H64   1024
#define HH    2048
#define G4    (4*HH)     // 8192

// ---------------- device scratch (static, no allocation) ----------------
__device__ float   d_s2 [BATCH*NPTS];
__device__ int     d_idx[BATCH*NPTS*4];
__device__ float   d_x  [BATCH*NPTS];
__device__ float   d_f  [BATCH*H16];
__device__ float   d_i  [BATCH*H64];
__device__ float   d_z  [BATCH*HH];
__device__ float   d_Zg [BATCH*G4];
__device__ float   d_hbuf[2][HH];
__device__ unsigned g_barcnt;
__device__ unsigned g_pad[31];      // separate cache lines
__device__ unsigned g_barphase;

// ---------------- GCN: per-node top-4 nearest + first conv ----------------
// grid 256 blocks x 256 threads; block = (sample b, quarter q)
__global__ void gcn_topk_kernel(const float* __restrict__ input,
                                const float* __restrict__ gc1_w,
                                const float* __restrict__ gc1_b,
                                const float* __restrict__ gc2_w)
{
    __shared__ float sx[NPTS];
    int b = blockIdx.x >> 2;
    int i = ((blockIdx.x & 3) << 8) + threadIdx.x;
    const float* xrow = input + b * NPTS;
    for (int j = threadIdx.x; j < NPTS; j += 256) sx[j] = xrow[j];
    __syncthreads();

    const float INF = __int_as_float(0x7f800000);
    float xi = sx[i];
    float d0 = INF, d1 = INF, d2 = INF, d3 = INF;
    int   i0 = 0,  i1 = 0,  i2 = 0,  i3 = 0;
    for (int j = 0; j < NPTS; ++j) {
        float d = fabsf(xi - sx[j]);
        if (j == i) continue;                 // diag = inf
        if (d < d3) {                          // strict < : jax tie-break (lower idx wins)
            if (d < d2) {
                d3 = d2; i3 = i2;
                if (d < d1) {
                    d2 = d1; i2 = i1;
                    if (d < d0) { d1 = d0; i1 = i0; d0 = d; i0 = j; }
                    else        { d1 = d;  i1 = j; }
                } else { d2 = d; i2 = j; }
            } else { d3 = d; i3 = j; }
        }
    }
    float S = sx[i0] + sx[i1] + sx[i2] + sx[i3];
    // h1_m = relu(S*w1_m + b1_m); s2 = sum_m h1_m * w2_m
    float s2 = 0.f;
    #pragma unroll
    for (int m = 0; m < 4; ++m) {
        float h1 = fmaxf(S * gc1_w[m] + gc1_b[m], 0.f);
        s2 += h1 * gc2_w[m];
    }
    int node = b * NPTS + i;
    d_s2[node] = s2;
    int4 id = make_int4(i0, i1, i2, i3);
    ((int4*)d_idx)[node] = id;
}

__global__ void gcn_gather_kernel(const float* __restrict__ gc2_b)
{
    int t = blockIdx.x * blockDim.x + threadIdx.x;   // 65536 total
    int4 id = ((const int4*)d_idx)[t];
    int base = (t >> 10) << 10;                       // b*1024
    d_x[t] = gc2_b[0] + d_s2[base + id.x] + d_s2[base + id.y]
                      + d_s2[base + id.z] + d_s2[base + id.w];
}

// ---------------- warp-per-output GEMM (small O) ----------------
// out[b,o] = relu( sum_k A[b,k]*W[o,k] + bias[o] )
// grid: (ceil(O/8), 4) ; block 256 ; blockIdx.y selects 16-batch chunk
__global__ void __launch_bounds__(256) wgemm_relu(const float* __restrict__ A,
                                                  const float* __restrict__ W,
                                                  const float* __restrict__ bias,
                                                  float* __restrict__ C,
                                                  int K, int O)
{
    int warp = threadIdx.x >> 5, lane = threadIdx.x & 31;
    int o = blockIdx.x * 8 + warp;
    if (o >= O) return;
    int bc = blockIdx.y * 16;
    const float* wr = W + (size_t)o * K;
    float acc[16];
    #pragma unroll
    for (int q = 0; q < 16; ++q) acc[q] = 0.f;
    for (int k = lane; k < K; k += 32) {
        float wv = wr[k];
        #pragma unroll
        for (int q = 0; q < 16; ++q) acc[q] = fmaf(wv, A[(size_t)(bc + q) * K + k], acc[q]);
    }
    #pragma unroll
    for (int q = 0; q < 16; ++q) {
        float v = acc[q];
        #pragma unroll
        for (int off = 16; off; off >>= 1) v += __shfl_down_sync(0xffffffffu, v, off);
        if (lane == 0) C[(size_t)(bc + q) * O + o] = fmaxf(v + bias[o], 0.f);
    }
}

// ---------------- tiled SGEMM: C(64,O) = A(64,K) @ W(O,K)^T ----------------
// BM=64 (full batch), BN=64, BK=32 ; 256 threads ; micro-tile 4x4
template<bool RELU, bool TWOB>
__global__ void __launch_bounds__(256, 1) sgemm64(const float* __restrict__ A,
                                                  const float* __restrict__ W,
                                                  const float* __restrict__ b1,
                                                  const float* __restrict__ b2,
                                                  float* __restrict__ C,
                                                  int K, int O)
{
    const int BK = 32, BN = 64;
    __shared__ float As[BK][68];
    __shared__ float Ws[BK][68];
    int tid = threadIdx.x;
    int tx = tid & 15, ty = tid >> 4;
    int b0 = ty * 4, oo0 = tx * 4;
    int o_blk = blockIdx.x * BN;

    float acc[4][4];
    #pragma unroll
    for (int a = 0; a < 4; ++a)
        #pragma unroll
        for (int bb = 0; bb < 4; ++bb) acc[a][bb] = 0.f;

    for (int k0 = 0; k0 < K; k0 += BK) {
        #pragma unroll
        for (int l = tid; l < 64 * BK / 4; l += 256) {
            int row = l >> 3, c4 = l & 7;
            float4 v = *(const float4*)(A + (size_t)row * K + k0 + c4 * 4);
            As[c4 * 4 + 0][row] = v.x; As[c4 * 4 + 1][row] = v.y;
            As[c4 * 4 + 2][row] = v.z; As[c4 * 4 + 3][row] = v.w;
        }
        #pragma unroll
        for (int l = tid; l < BN * BK / 4; l += 256) {
            int row = l >> 3, c4 = l & 7;
            float4 v = *(const float4*)(W + (size_t)(o_blk + row) * K + k0 + c4 * 4);
            Ws[c4 * 4 + 0][row] = v.x; Ws[c4 * 4 + 1][row] = v.y;
            Ws[c4 * 4 + 2][row] = v.z; Ws[c4 * 4 + 3][row] = v.w;
        }
        __syncthreads();
        #pragma unroll
        for (int kk = 0; kk < BK; ++kk) {
            float a0 = As[kk][b0], a1 = As[kk][b0 + 1], a2 = As[kk][b0 + 2], a3 = As[kk][b0 + 3];
            float w0 = Ws[kk][oo0], w1 = Ws[kk][oo0 + 1], w2 = Ws[kk][oo0 + 2], w3 = Ws[kk][oo0 + 3];
            acc[0][0] += a0 * w0; acc[0][1] += a0 * w1; acc[0][2] += a0 * w2; acc[0][3] += a0 * w3;
            acc[1][0] += a1 * w0; acc[1][1] += a1 * w1; acc[1][2] += a1 * w2; acc[1][3] += a1 * w3;
            acc[2][0] += a2 * w0; acc[2][1] += a2 * w1; acc[2][2] += a2 * w2; acc[2][3] += a2 * w3;
            acc[3][0] += a3 * w0; acc[3][1] += a3 * w1; acc[3][2] += a3 * w2; acc[3][3] += a3 * w3;
        }
        __syncthreads();
    }
    #pragma unroll
    for (int j = 0; j < 4; ++j) {
        int o = o_blk + oo0 + j;
        float bs = b1[o] + (TWOB ? b2[o] : 0.f);
        #pragma unroll
        for (int a = 0; a < 4; ++a) {
            float v = acc[a][j] + bs;
            if (RELU) v = fmaxf(v, 0.f);
            C[(size_t)(b0 + a) * O + o] = v;
        }
    }
}

// ---------------- persistent LSTM ----------------
__device__ __forceinline__ float sigf(float x) { return 1.f / (1.f + __expf(-x)); }
__device__ __forceinline__ float tanh_fast(float x) {
    float ax = fabsf(x);
    float e = __expf(2.f * ax);
    float t = 1.f - 2.f / (e + 1.f);
    return (x < 0.f) ? -t : t;
}

__device__ __forceinline__ void grid_barrier(unsigned nblocks)
{
    __threadfence();
    __syncthreads();
    if (threadIdx.x == 0) {
        unsigned p = *(volatile unsigned*)&g_barphase;
        unsigned old = atomicAdd(&g_barcnt, 1u);
        if (old == nblocks - 1u) {
            atomicExch(&g_barcnt, 0u);
            __threadfence();
            atomicAdd(&g_barphase, 1u);
        } else {
            while (*(volatile unsigned*)&g_barphase == p) { __nanosleep(32); }
        }
    }
    __threadfence();
    __syncthreads();
}

// grid: 128 blocks x 512 threads (<= SM count -> co-resident). warp u owns unit u.
__global__ void __launch_bounds__(512, 1) lstm_kernel(const float* __restrict__ w_hh,
                                                      float* __restrict__ out)
{
    __shared__ float sh[HH];
    int tid = threadIdx.x, lane = tid & 31, warp = tid >> 5;
    int u = (blockIdx.x << 4) + warp;          // 0..2047
    const float* w0 = w_hh + (size_t)u * HH;
    const float* w1 = w0 + (size_t)HH * HH;
    const float* w2 = w1 + (size_t)HH * HH;
    const float* w3 = w2 + (size_t)HH * HH;

    float c = 0.f;
    for (int t = 0; t < BATCH; ++t) {
        float s0 = 0.f, s1 = 0.f, s2 = 0.f, s3 = 0.f;
        if (t) {
            const float4* hsrc = (const float4*)d_hbuf[(t - 1) & 1];
            ((float4*)sh)[tid] = __ldcg(hsrc + tid);   // 512 float4 = 2048 floats
            __syncthreads();
            #pragma unroll 4
            for (int q = 0; q < 16; ++q) {
                int k = q * 128 + lane * 4;
                float4 h4 = *(const float4*)(sh + k);
                float4 a;
                a = *(const float4*)(w0 + k);
                s0 += h4.x * a.x + h4.y * a.y + h4.z * a.z + h4.w * a.w;
                a = *(const float4*)(w1 + k);
                s1 += h4.x * a.x + h4.y * a.y + h4.z * a.z + h4.w * a.w;
                a = *(const float4*)(w2 + k);
                s2 += h4.x * a.x + h4.y * a.y + h4.z * a.z + h4.w * a.w;
                a = *(const float4*)(w3 + k);
                s3 += h4.x * a.x + h4.y * a.y + h4.z * a.z + h4.w * a.w;
            }
            #pragma unroll
            for (int off = 16; off; off >>= 1) {
                s0 += __shfl_down_sync(0xffffffffu, s0, off);
                s1 += __shfl_down_sync(0xffffffffu, s1, off);
                s2 += __shfl_down_sync(0xffffffffu, s2, off);
                s3 += __shfl_down_sync(0xffffffffu, s3, off);
            }
        }
        if (lane == 0) {
            const float* Z = d_Zg + (size_t)t * G4;
            float xi = Z[u]            + s0;
            float xf = Z[u + HH]       + s1;
            float xg = Z[u + 2 * HH]   + s2;
            float xo = Z[u + 3 * HH]   + s3;
            c = sigf(xf) * c + sigf(xi) * tanh_fast(xg);
            float h = sigf(xo) * tanh_fast(c);
            __stcg(&d_hbuf[t & 1][u], h);
            out[(size_t)t * HH + u] = h;
        }
        grid_barrier(gridDim.x);
    }
}

// ---------------- launch ----------------
extern "C" void kernel_launch(void* const* d_in, const int* in_sizes, int n_in,
                              void* d_out, int out_size)
{
    const float* input = (const float*)d_in[0];
    const float* gc1_w = (const float*)d_in[3];
    const float* gc1_b = (const float*)d_in[4];
    const float* gc2_w = (const float*)d_in[5];
    const float* gc2_b = (const float*)d_in[6];
    const float* fl_w  = (const float*)d_in[7];
    const float* fl_b  = (const float*)d_in[8];
    const float* il_w  = (const float*)d_in[9];
    const float* il_b  = (const float*)d_in[10];
    const float* ol_w  = (const float*)d_in[11];
    const float* ol_b  = (const float*)d_in[12];
    const float* w_ih  = (const float*)d_in[13];
    const float* w_hh  = (const float*)d_in[14];
    const float* b_ih  = (const float*)d_in[15];
    const float* b_hh  = (const float*)d_in[16];
    float* out = (float*)d_out;

    float* s_x;  cudaGetSymbolAddress((void**)&s_x,  d_x);
    float* s_f;  cudaGetSymbolAddress((void**)&s_f,  d_f);
    float* s_i;  cudaGetSymbolAddress((void**)&s_i,  d_i);
    float* s_z;  cudaGetSymbolAddress((void**)&s_z,  d_z);
    float* s_Zg; cudaGetSymbolAddress((void**)&s_Zg, d_Zg);

    gcn_topk_kernel<<<256, 256>>>(input, gc1_w, gc1_b, gc2_w);
    gcn_gather_kernel<<<256, 256>>>(gc2_b);

    // f = relu(x @ fl_w^T + fl_b)      (64,256)
    wgemm_relu<<<dim3(32, 4), 256>>>(s_x, fl_w, fl_b, s_f, NPTS, H16);
    // i = relu(f @ il_w^T + il_b)      (64,1024)
    wgemm_relu<<<dim3(128, 4), 256>>>(s_f, il_w, il_b, s_i, H16, H64);
    // z = relu(i @ ol_w^T + ol_b)      (64,2048)
    sgemm64<true, false><<<HH / 64, 256>>>(s_i, ol_w, ol_b, nullptr, s_z, H64, HH);
    // Zg = z @ w_ih^T + b_ih + b_hh    (64,8192)
    sgemm64<false, true><<<G4 / 64, 256>>>(s_z, w_ih, b_ih, b_hh, s_Zg, HH, G4);

    lstm_kernel<<<128, 512>>>(w_hh, out);
}

// round 2
// speedup vs baseline: 1.0895x; 1.0895x over previous
#include <cuda_runtime.h>
#include <cuda_bf16.h>
#include <cstdint>

#define BATCH 64
#define NPTS  1024
#define H16   256
#define H64   1024
#define HH    2048
#define G4    (4*HH)     // 8192
#define NBLK  128

// ---------------- device scratch (static, no allocation) ----------------
__device__ float   d_s2 [BATCH*NPTS];
__device__ int     d_idx[BATCH*NPTS*4];
__device__ float   d_x  [BATCH*NPTS];
__device__ float   d_f  [BATCH*H16];
__device__ float   d_i  [BATCH*H64];
__device__ float   d_z  [BATCH*HH];
__device__ float   d_Zg [BATCH*G4];
__device__ float   d_hbuf[2][HH];
__device__ __nv_bfloat16 d_wpack[(size_t)4*HH*HH];   // 32MB, per-unit gate-contiguous
__device__ volatile unsigned g_arrive[NBLK];
__device__ volatile unsigned g_release;

// ---------------- GCN: per-node top-4 nearest + first conv ----------------
__global__ void gcn_topk_kernel(const float* __restrict__ input,
                                const float* __restrict__ gc1_w,
                                const float* __restrict__ gc1_b,
                                const float* __restrict__ gc2_w)
{
    __shared__ float sx[NPTS];
    int b = blockIdx.x >> 2;
    int i = ((blockIdx.x & 3) << 8) + threadIdx.x;
    const float* xrow = input + b * NPTS;
    for (int j = threadIdx.x; j < NPTS; j += 256) sx[j] = xrow[j];
    __syncthreads();

    const float INF = __int_as_float(0x7f800000);
    float xi = sx[i];
    float d0 = INF, d1 = INF, d2 = INF, d3 = INF;
    int   i0 = 0,  i1 = 0,  i2 = 0,  i3 = 0;
    for (int j = 0; j < NPTS; ++j) {
        float d = fabsf(xi - sx[j]);
        if (j == i) continue;
        if (d < d3) {
            if (d < d2) {
                d3 = d2; i3 = i2;
                if (d < d1) {
                    d2 = d1; i2 = i1;
                    if (d < d0) { d1 = d0; i1 = i0; d0 = d; i0 = j; }
                    else        { d1 = d;  i1 = j; }
                } else { d2 = d; i2 = j; }
            } else { d3 = d; i3 = j; }
        }
    }
    float S = sx[i0] + sx[i1] + sx[i2] + sx[i3];
    float s2 = 0.f;
    #pragma unroll
    for (int m = 0; m < 4; ++m) {
        float h1 = fmaxf(S * gc1_w[m] + gc1_b[m], 0.f);
        s2 += h1 * gc2_w[m];
    }
    int node = b * NPTS + i;
    d_s2[node] = s2;
    ((int4*)d_idx)[node] = make_int4(i0, i1, i2, i3);
}

__global__ void gcn_gather_kernel(const float* __restrict__ gc2_b)
{
    int t = blockIdx.x * blockDim.x + threadIdx.x;
    int4 id = ((const int4*)d_idx)[t];
    int base = (t >> 10) << 10;
    d_x[t] = gc2_b[0] + d_s2[base + id.x] + d_s2[base + id.y]
                      + d_s2[base + id.z] + d_s2[base + id.w];
}

// ---------------- warp-per-output GEMM (small O) ----------------
__global__ void __launch_bounds__(256) wgemm_relu(const float* __restrict__ A,
                                                  const float* __restrict__ W,
                                                  const float* __restrict__ bias,
                                                  float* __restrict__ C,
                                                  int K, int O)
{
    int warp = threadIdx.x >> 5, lane = threadIdx.x & 31;
    int o = blockIdx.x * 8 + warp;
    if (o >= O) return;
    int bc = blockIdx.y * 16;
    const float* wr = W + (size_t)o * K;
    float acc[16];
    #pragma unroll
    for (int q = 0; q < 16; ++q) acc[q] = 0.f;
    for (int k = lane; k < K; k += 32) {
        float wv = wr[k];
        #pragma unroll
        for (int q = 0; q < 16; ++q) acc[q] = fmaf(wv, A[(size_t)(bc + q) * K + k], acc[q]);
    }
    #pragma unroll
    for (int q = 0; q < 16; ++q) {
        float v = acc[q];
        #pragma unroll
        for (int off = 16; off; off >>= 1) v += __shfl_down_sync(0xffffffffu, v, off);
        if (lane == 0) C[(size_t)(bc + q) * O + o] = fmaxf(v + bias[o], 0.f);
    }
}

// ---------------- tiled SGEMM: C(64,O) = A(64,K) @ W(O,K)^T ----------------
template<bool RELU, bool TWOB>
__global__ void __launch_bounds__(256, 1) sgemm64(const float* __restrict__ A,
                                                  const float* __restrict__ W,
                                                  const float* __restrict__ b1,
                                                  const float* __restrict__ b2,
                                                  float* __restrict__ C,
                                                  int K, int O)
{
    const int BK = 32, BN = 64;
    __shared__ float As[BK][68];
    __shared__ float Ws[BK][68];
    int tid = threadIdx.x;
    int tx = tid & 15, ty = tid >> 4;
    int b0 = ty * 4, oo0 = tx * 4;
    int o_blk = blockIdx.x * BN;

    float acc[4][4];
    #pragma unroll
    for (int a = 0; a < 4; ++a)
        #pragma unroll
        for (int bb = 0; bb < 4; ++bb) acc[a][bb] = 0.f;

    for (int k0 = 0; k0 < K; k0 += BK) {
        #pragma unroll
        for (int l = tid; l < 64 * BK / 4; l += 256) {
            int row = l >> 3, c4 = l & 7;
            float4 v = *(const float4*)(A + (size_t)row * K + k0 + c4 * 4);
            As[c4 * 4 + 0][row] = v.x; As[c4 * 4 + 1][row] = v.y;
            As[c4 * 4 + 2][row] = v.z; As[c4 * 4 + 3][row] = v.w;
        }
        #pragma unroll
        for (int l = tid; l < BN * BK / 4; l += 256) {
            int row = l >> 3, c4 = l & 7;
            float4 v = *(const float4*)(W + (size_t)(o_blk + row) * K + k0 + c4 * 4);
            Ws[c4 * 4 + 0][row] = v.x; Ws[c4 * 4 + 1][row] = v.y;
            Ws[c4 * 4 + 2][row] = v.z; Ws[c4 * 4 + 3][row] = v.w;
        }
        __syncthreads();
        #pragma unroll
        for (int kk = 0; kk < BK; ++kk) {
            float a0 = As[kk][b0], a1 = As[kk][b0 + 1], a2 = As[kk][b0 + 2], a3 = As[kk][b0 + 3];
            float w0 = Ws[kk][oo0], w1 = Ws[kk][oo0 + 1], w2 = Ws[kk][oo0 + 2], w3 = Ws[kk][oo0 + 3];
            acc[0][0] += a0 * w0; acc[0][1] += a0 * w1; acc[0][2] += a0 * w2; acc[0][3] += a0 * w3;
            acc[1][0] += a1 * w0; acc[1][1] += a1 * w1; acc[1][2] += a1 * w2; acc[1][3] += a1 * w3;
            acc[2][0] += a2 * w0; acc[2][1] += a2 * w1; acc[2][2] += a2 * w2; acc[2][3] += a2 * w3;
            acc[3][0] += a3 * w0; acc[3][1] += a3 * w1; acc[3][2] += a3 * w2; acc[3][3] += a3 * w3;
        }
        __syncthreads();
    }
    #pragma unroll
    for (int j = 0; j < 4; ++j) {
        int o = o_blk + oo0 + j;
        float bs = b1[o] + (TWOB ? b2[o] : 0.f);
        #pragma unroll
        for (int a = 0; a < 4; ++a) {
            float v = acc[a][j] + bs;
            if (RELU) v = fmaxf(v, 0.f);
            C[(size_t)(b0 + a) * O + o] = v;
        }
    }
}

// ---------------- w_hh fp32 -> packed bf16 (per-unit gate-contiguous) ----------------
// src row r = g*HH + u  ->  dst block (u*4 + g)
__global__ void __launch_bounds__(256) convert_whh(const float* __restrict__ w,
                                                   __nv_bfloat16* __restrict__ wp)
{
    int r = blockIdx.x;                  // 0..8191
    int g = r >> 11, u = r & (HH - 1);
    const float4* src = (const float4*)(w + (size_t)r * HH);
    __nv_bfloat16* dst = wp + ((size_t)u * 4 + g) * HH;
    int t = threadIdx.x;                 // 256 threads * 8 elems
    float4 a = src[t * 2], b = src[t * 2 + 1];
    __nv_bfloat162 p0 = __floats2bfloat162_rn(a.x, a.y);
    __nv_bfloat162 p1 = __floats2bfloat162_rn(a.z, a.w);
    __nv_bfloat162 p2 = __floats2bfloat162_rn(b.x, b.y);
    __nv_bfloat162 p3 = __floats2bfloat162_rn(b.z, b.w);
    uint4 o;
    o.x = *(unsigned*)&p0; o.y = *(unsigned*)&p1;
    o.z = *(unsigned*)&p2; o.w = *(unsigned*)&p3;
    ((uint4*)dst)[t] = o;
}

// ---------------- persistent LSTM ----------------
__device__ __forceinline__ float sigf(float x) { return 1.f / (1.f + __expf(-x)); }
__device__ __forceinline__ float tanh_fast(float x) {
    float ax = fabsf(x);
    float e = __expf(2.f * ax);
    float t = 1.f - 2.f / (e + 1.f);
    return (x < 0.f) ? -t : t;
}

// flag-tree grid barrier; equality compare makes it graph-replay safe
// (stale value 64 from previous replay never equals step 1..64 freshly needed)
__device__ __forceinline__ void grid_barrier(unsigned step)
{
    __syncthreads();
    if (blockIdx.x == 0) {
        if (threadIdx.x == 0) { __threadfence(); g_arrive[0] = step; }
        if (threadIdx.x < NBLK) {
            while (g_arrive[threadIdx.x] != step) { }
        }
        __syncthreads();
        if (threadIdx.x == 0) { __threadfence(); g_release = step; }
    } else {
        if (threadIdx.x == 0) {
            __threadfence();
            g_arrive[blockIdx.x] = step;
            while (g_release != step) { }
        }
    }
    __syncthreads();
}

__device__ __forceinline__ float dot8(const __nv_bfloat16* __restrict__ p,
                                      float4 ha, float4 hb)
{
    uint4 w = *(const uint4*)p;
    float2 f0 = __bfloat1622float2(*(__nv_bfloat162*)&w.x);
    float2 f1 = __bfloat1622float2(*(__nv_bfloat162*)&w.y);
    float2 f2 = __bfloat1622float2(*(__nv_bfloat162*)&w.z);
    float2 f3 = __bfloat1622float2(*(__nv_bfloat162*)&w.w);
    return ha.x * f0.x + ha.y * f0.y + ha.z * f1.x + ha.w * f1.y
         + hb.x * f2.x + hb.y * f2.y + hb.z * f3.x + hb.w * f3.y;
}

// grid: 128 blocks x 512 threads (co-resident). warp owns unit u; c in register.
__global__ void __launch_bounds__(512, 1) lstm_kernel(float* __restrict__ out)
{
    __shared__ float sh[HH];
    int tid = threadIdx.x, lane = tid & 31, warp = tid >> 5;
    int u = (blockIdx.x << 4) + warp;                 // 0..2047
    const __nv_bfloat16* wu = d_wpack + (size_t)u * 4 * HH;

    float c = 0.f;
    for (int t = 0; t < BATCH; ++t) {
        float s0 = 0.f, s1 = 0.f, s2 = 0.f, s3 = 0.f;
        if (t) {
            const float4* hsrc = (const float4*)d_hbuf[(t - 1) & 1];
            ((float4*)sh)[tid] = __ldcg(hsrc + tid);
            __syncthreads();
            #pragma unroll
            for (int q = 0; q < 8; ++q) {
                int k = q * 256 + lane * 8;
                float4 ha = *(const float4*)(sh + k);
                float4 hb = *(const float4*)(sh + k + 4);
                const __nv_bfloat16* base = wu + k;
                s0 += dot8(base,          ha, hb);
                s1 += dot8(base + HH,     ha, hb);
                s2 += dot8(base + 2 * HH, ha, hb);
                s3 += dot8(base + 3 * HH, ha, hb);
            }
            #pragma unroll
            for (int off = 16; off; off >>= 1) {
                s0 += __shfl_down_sync(0xffffffffu, s0, off);
                s1 += __shfl_down_sync(0xffffffffu, s1, off);
                s2 += __shfl_down_sync(0xffffffffu, s2, off);
                s3 += __shfl_down_sync(0xffffffffu, s3, off);
            }
        }
        if (lane == 0) {
            const float* Z = d_Zg + (size_t)t * G4;
            float xi = Z[u]          + s0;
            float xf = Z[u + HH]     + s1;
            float xg = Z[u + 2 * HH] + s2;
            float xo = Z[u + 3 * HH] + s3;
            c = sigf(xf) * c + sigf(xi) * tanh_fast(xg);
            float h = sigf(xo) * tanh_fast(c);
            __stcg(&d_hbuf[t & 1][u], h);
            out[(size_t)t * HH + u] = h;
            __threadfence();              // h globally visible before barrier arrive
        }
        grid_barrier((unsigned)(t + 1));
    }
}

// ---------------- launch ----------------
extern "C" void kernel_launch(void* const* d_in, const int* in_sizes, int n_in,
                              void* d_out, int out_size)
{
    const float* input = (const float*)d_in[0];
    const float* gc1_w = (const float*)d_in[3];
    const float* gc1_b = (const float*)d_in[4];
    const float* gc2_w = (const float*)d_in[5];
    const float* gc2_b = (const float*)d_in[6];
    const float* fl_w  = (const float*)d_in[7];
    const float* fl_b  = (const float*)d_in[8];
    const float* il_w  = (const float*)d_in[9];
    const float* il_b  = (const float*)d_in[10];
    const float* ol_w  = (const float*)d_in[11];
    const float* ol_b  = (const float*)d_in[12];
    const float* w_ih  = (const float*)d_in[13];
    const float* w_hh  = (const float*)d_in[14];
    const float* b_ih  = (const float*)d_in[15];
    const float* b_hh  = (const float*)d_in[16];
    float* out = (float*)d_out;

    float* s_x;  cudaGetSymbolAddress((void**)&s_x,  d_x);
    float* s_f;  cudaGetSymbolAddress((void**)&s_f,  d_f);
    float* s_i;  cudaGetSymbolAddress((void**)&s_i,  d_i);
    float* s_z;  cudaGetSymbolAddress((void**)&s_z,  d_z);
    float* s_Zg; cudaGetSymbolAddress((void**)&s_Zg, d_Zg);
    __nv_bfloat16* s_wp; cudaGetSymbolAddress((void**)&s_wp, d_wpack);

    // weight pack can run first (independent of activations)
    convert_whh<<<G4, 256>>>(w_hh, s_wp);

    gcn_topk_kernel<<<256, 256>>>(input, gc1_w, gc1_b, gc2_w);
    gcn_gather_kernel<<<256, 256>>>(gc2_b);

    wgemm_relu<<<dim3(32, 4), 256>>>(s_x, fl_w, fl_b, s_f, NPTS, H16);
    wgemm_relu<<<dim3(128, 4), 256>>>(s_f, il_w, il_b, s_i, H16, H64);
    sgemm64<true, false><<<HH / 64, 256>>>(s_i, ol_w, ol_b, nullptr, s_z, H64, HH);
    sgemm64<false, true><<<G4 / 64, 256>>>(s_z, w_ih, b_ih, b_hh, s_Zg, HH, G4);

    lstm_kernel<<<NBLK, 512>>>(out);
}

// round 4
// speedup vs baseline: 1.1337x; 1.0406x over previous
#include <cuda_runtime.h>
#include <cuda_bf16.h>
#include <cstdint>

#define BATCH 64
#define NPTS  1024
#define H16   256
#define H64   1024
#define HH    2048
#define G4    (4*HH)     // 8192
#define NBLK  128

// ---------------- device scratch (static, no allocation) ----------------
__device__ float d_xT[NPTS*BATCH];     // 1024 x 64
__device__ float d_fT[H16*BATCH];      // 256 x 64   (relu applied)
__device__ float d_iT[H64*BATCH];      // 1024 x 64  (relu applied)
__device__ float d_zT[HH*BATCH];       // 2048 x 64  (relu applied)
__device__ float d_Zg[BATCH*G4];       // 64 x 8192
__device__ float d_hbuf[2][HH];
__device__ volatile unsigned g_arrive[NBLK];
__device__ volatile unsigned g_release;

// ---------------- GCN fused: topk + conv1 + gather + conv2 ----------------
// one block per sample, 1024 threads
__global__ void __launch_bounds__(1024) gcn_all(const float* __restrict__ input,
                                                const float* __restrict__ gc1_w,
                                                const float* __restrict__ gc1_b,
                                                const float* __restrict__ gc2_w,
                                                const float* __restrict__ gc2_b,
                                                float* __restrict__ xT)
{
    __shared__ float sx[NPTS];
    __shared__ float ss2[NPTS];
    int b = blockIdx.x;
    int i = threadIdx.x;
    sx[i] = input[b * NPTS + i];
    __syncthreads();

    const float INF = __int_as_float(0x7f800000);
    float xi = sx[i];
    float d0 = INF, d1 = INF, d2 = INF, d3 = INF;
    int   i0 = 0,  i1 = 0,  i2 = 0,  i3 = 0;
    for (int j = 0; j < NPTS; ++j) {
        float d = fabsf(xi - sx[j]);
        if (j == i) continue;
        if (d < d3) {                       // strict < : lower idx wins ties (jax)
            if (d < d2) {
                d3 = d2; i3 = i2;
                if (d < d1) {
                    d2 = d1; i2 = i1;
                    if (d < d0) { d1 = d0; i1 = i0; d0 = d; i0 = j; }
                    else        { d1 = d;  i1 = j; }
                } else { d2 = d; i2 = j; }
            } else { d3 = d; i3 = j; }
        }
    }
    float S = sx[i0] + sx[i1] + sx[i2] + sx[i3];
    float s2 = 0.f;
    #pragma unroll
    for (int m = 0; m < 4; ++m) {
        float h1 = fmaxf(S * gc1_w[m] + gc1_b[m], 0.f);
        s2 += h1 * gc2_w[m];
    }
    ss2[i] = s2;
    __syncthreads();
    float v = gc2_b[0] + ss2[i0] + ss2[i1] + ss2[i2] + ss2[i3];
    xT[i * BATCH + b] = v;                 // transposed output
}

// ---------------- gemvT: outT(O,64) = [relu](W(O,K) @ AT(K,64) + bias) ----------------
// warp per (output o, 32-batch half); weight loads lane-uniform, AT loads coalesced
template<bool RELU>
__global__ void __launch_bounds__(256) gemvT(const float* __restrict__ AT,
                                             const float* __restrict__ W,
                                             const float* __restrict__ bias,
                                             float* __restrict__ outT,
                                             int K, int O)
{
    int gw = blockIdx.x * 8 + (threadIdx.x >> 5);
    int lane = threadIdx.x & 31;
    int o = gw >> 1;
    if (o >= O) return;
    int b = ((gw & 1) << 5) + lane;
    const float* wr = W + (size_t)o * K;
    const float* ac = AT + b;
    float acc0 = 0.f, acc1 = 0.f;
    for (int k = 0; k < K; k += 8) {
        float4 wa = *(const float4*)(wr + k);
        float4 wb = *(const float4*)(wr + k + 4);
        acc0 += wa.x * ac[(k + 0) * BATCH] + wa.y * ac[(k + 1) * BATCH]
              + wa.z * ac[(k + 2) * BATCH] + wa.w * ac[(k + 3) * BATCH];
        acc1 += wb.x * ac[(k + 4) * BATCH] + wb.y * ac[(k + 5) * BATCH]
              + wb.z * ac[(k + 6) * BATCH] + wb.w * ac[(k + 7) * BATCH];
    }
    float v = acc0 + acc1 + bias[o];
    if (RELU) v = fmaxf(v, 0.f);
    outT[(size_t)o * BATCH + b] = v;
}

// ---------------- tiled SGEMM (AT input): C(64,O) = AT(K,64)^T @ W(O,K)^T ----------------
__global__ void __launch_bounds__(256, 1) sgemmAT(const float* __restrict__ AT,
                                                  const float* __restrict__ W,
                                                  const float* __restrict__ b1,
                                                  const float* __restrict__ b2,
                                                  float* __restrict__ C,
                                                  int K, int O)
{
    const int BK = 32, BN = 64;
    __shared__ float As[BK][72];
    __shared__ float Ws[BK][72];
    int tid = threadIdx.x;
    int tx = tid & 15, ty = tid >> 4;
    int b0 = ty * 4, oo0 = tx * 4;
    int o_blk = blockIdx.x * BN;

    float acc[4][4];
    #pragma unroll
    for (int a = 0; a < 4; ++a)
        #pragma unroll
        for (int bb = 0; bb < 4; ++bb) acc[a][bb] = 0.f;

    for (int k0 = 0; k0 < K; k0 += BK) {
        #pragma unroll
        for (int l = tid; l < BK * 64 / 4; l += 256) {
            int kk = l >> 4, b4 = l & 15;
            float4 v = *(const float4*)(AT + (size_t)(k0 + kk) * BATCH + b4 * 4);
            *(float4*)&As[kk][b4 * 4] = v;
        }
        #pragma unroll
        for (int l = tid; l < BN * BK / 4; l += 256) {
            int row = l >> 3, c4 = l & 7;
            float4 v = *(const float4*)(W + (size_t)(o_blk + row) * K + k0 + c4 * 4);
            Ws[c4 * 4 + 0][row] = v.x; Ws[c4 * 4 + 1][row] = v.y;
            Ws[c4 * 4 + 2][row] = v.z; Ws[c4 * 4 + 3][row] = v.w;
        }
        __syncthreads();
        #pragma unroll
        for (int kk = 0; kk < BK; ++kk) {
            float a0 = As[kk][b0], a1 = As[kk][b0 + 1], a2 = As[kk][b0 + 2], a3 = As[kk][b0 + 3];
            float w0 = Ws[kk][oo0], w1 = Ws[kk][oo0 + 1], w2 = Ws[kk][oo0 + 2], w3 = Ws[kk][oo0 + 3];
            acc[0][0] += a0 * w0; acc[0][1] += a0 * w1; acc[0][2] += a0 * w2; acc[0][3] += a0 * w3;
            acc[1][0] += a1 * w0; acc[1][1] += a1 * w1; acc[1][2] += a1 * w2; acc[1][3] += a1 * w3;
            acc[2][0] += a2 * w0; acc[2][1] += a2 * w1; acc[2][2] += a2 * w2; acc[2][3] += a2 * w3;
            acc[3][0] += a3 * w0; acc[3][1] += a3 * w1; acc[3][2] += a3 * w2; acc[3][3] += a3 * w3;
        }
        __syncthreads();
    }
    #pragma unroll
    for (int j = 0; j < 4; ++j) {
        int o = o_blk + oo0 + j;
        float bs = b1[o] + b2[o];
        #pragma unroll
        for (int a = 0; a < 4; ++a)
            C[(size_t)(b0 + a) * O + o] = acc[a][j] + bs;
    }
}

// ---------------- persistent LSTM, SMEM-resident weights ----------------
__device__ __forceinline__ float sigf(float x) { return 1.f / (1.f + __expf(-x)); }
__device__ __forceinline__ float tanh_fast(float x) {
    float ax = fabsf(x);
    float e = __expf(2.f * ax);
    float t = 1.f - 2.f / (e + 1.f);
    return (x < 0.f) ? -t : t;
}

// flag barrier; equality compare is graph-replay safe (stale==64 only aliases
// the FINAL barrier, after which no block does dependent work)
__device__ __forceinline__ void grid_barrier(unsigned step)
{
    __syncthreads();
    if (blockIdx.x == 0) {
        if (threadIdx.x == 0) { __threadfence(); g_arrive[0] = step; }
        if (threadIdx.x < NBLK) {
            while (g_arrive[threadIdx.x] != step) { __nanosleep(20); }
        }
        __syncthreads();
        if (threadIdx.x == 0) { __threadfence(); g_release = step; }
    } else {
        if (threadIdx.x == 0) {
            __threadfence();
            g_arrive[blockIdx.x] = step;
            while (g_release != step) { __nanosleep(20); }
        }
    }
    __syncthreads();
}

// SMEM layout (dynamic): [0, 192KB) = 48 rows (16 units x gates i,f,g) of 2048 bf16
//                        [192KB, 200KB) = h vector, 2048 f32
#define SMEM_W_BYTES (48 * 4096)
#define SMEM_TOTAL   (SMEM_W_BYTES + HH * 4)

// grid: 128 blocks x 256 threads (8 warps, 2 units/warp, 16 units/block)
__global__ void __launch_bounds__(256, 1) lstm_kernel(const float* __restrict__ w_hh,
                                                      float* __restrict__ out)
{
    extern __shared__ char smem[];
    float* shH = (float*)(smem + SMEM_W_BYTES);
    int tid = threadIdx.x, lane = tid & 31, warp = tid >> 5;
    int s0 = warp * 2;                        // unit slots s0, s0+1
    int ublk = (blockIdx.x << 4);

    // ---- preload: gates i,f,g (fp32 -> bf16) into SMEM, cooperative ----
    for (int r48 = 0; r48 < 48; ++r48) {
        int s = r48 / 3, g = r48 % 3;
        const float* src = w_hh + ((size_t)g * HH + (ublk + s)) * HH;
        char* dst = smem + r48 * 4096;
        #pragma unroll
        for (int j = tid; j < 512; j += 256) {
            float4 v = *(const float4*)(src + j * 4);
            __nv_bfloat162 p0 = __floats2bfloat162_rn(v.x, v.y);
            __nv_bfloat162 p1 = __floats2bfloat162_rn(v.z, v.w);
            uint2 pk;
            pk.x = *(unsigned*)&p0; pk.y = *(unsigned*)&p1;
            *(uint2*)(dst + j * 8) = pk;
        }
    }
    // ---- preload: o-gate into registers (bf16-packed), per warp 2 units ----
    uint2 og[2][16];
    #pragma unroll
    for (int r = 0; r < 2; ++r) {
        int u = ublk + s0 + r;
        const float* src = w_hh + ((size_t)3 * HH + u) * HH;
        #pragma unroll
        for (int q = 0; q < 16; ++q) {
            float4 v = *(const float4*)(src + q * 128 + lane * 4);
            __nv_bfloat162 p0 = __floats2bfloat162_rn(v.x, v.y);
            __nv_bfloat162 p1 = __floats2bfloat162_rn(v.z, v.w);
            og[r][q].x = *(unsigned*)&p0; og[r][q].y = *(unsigned*)&p1;
        }
    }
    __syncthreads();

    const char* w0base = smem + (size_t)(s0 * 3) * 4096;       // unit s0 gates
    const char* w1base = smem + (size_t)((s0 + 1) * 3) * 4096; // unit s0+1 gates

    float c = 0.f;                              // valid in lanes 0,1 (their unit)
    int myu = ublk + s0 + lane;                 // meaningful for lane<2

    for (int t = 0; t < BATCH; ++t) {
        // prefetch this step's Zg for lanes 0,1
        float z0 = 0.f, z1 = 0.f, z2 = 0.f, z3 = 0.f;
        if (lane < 2) {
            const float* Z = d_Zg + (size_t)t * G4 + myu;
            z0 = __ldg(Z); z1 = __ldg(Z + HH); z2 = __ldg(Z + 2 * HH); z3 = __ldg(Z + 3 * HH);
        }

        float a00 = 0.f, a01 = 0.f, a02 = 0.f, a03 = 0.f;
        float a10 = 0.f, a11 = 0.f, a12 = 0.f, a13 = 0.f;
        if (t) {
            // broadcast h into SMEM (L2-coherent load)
            const float4* hsrc = (const float4*)d_hbuf[(t - 1) & 1];
            #pragma unroll
            for (int j = tid; j < 512; j += 256)
                ((float4*)shH)[j] = __ldcg(hsrc + j);
            __syncthreads();

            #pragma unroll
            for (int q = 0; q < 16; ++q) {
                int k = q * 128 + lane * 4;
                float4 h4 = *(const float4*)(shH + k);
                int off = q * 256 + lane * 8;
                #define DOT(dst, PTR) { \
                    uint2 wv = *(const uint2*)(PTR); \
                    float2 fa = __bfloat1622float2(*(const __nv_bfloat162*)&wv.x); \
                    float2 fb = __bfloat1622float2(*(const __nv_bfloat162*)&wv.y); \
                    dst += h4.x * fa.x + h4.y * fa.y + h4.z * fb.x + h4.w * fb.y; }
                DOT(a00, w0base + off)
                DOT(a01, w0base + 4096 + off)
                DOT(a02, w0base + 8192 + off)
                DOT(a10, w1base + off)
                DOT(a11, w1base + 4096 + off)
                DOT(a12, w1base + 8192 + off)
                { // o-gates from registers
                    float2 fa = __bfloat1622float2(*(const __nv_bfloat162*)&og[0][q].x);
                    float2 fb = __bfloat1622float2(*(const __nv_bfloat162*)&og[0][q].y);
                    a03 += h4.x * fa.x + h4.y * fa.y + h4.z * fb.x + h4.w * fb.y;
                    float2 ga = __bfloat1622float2(*(const __nv_bfloat162*)&og[1][q].x);
                    float2 gb = __bfloat1622float2(*(const __nv_bfloat162*)&og[1][q].y);
                    a13 += h4.x * ga.x + h4.y * ga.y + h4.z * gb.x + h4.w * gb.y;
                }
                #undef DOT
            }
            // butterfly reductions (results valid in all lanes)
            #pragma unroll
            for (int off = 16; off; off >>= 1) {
                a00 += __shfl_xor_sync(0xffffffffu, a00, off);
                a01 += __shfl_xor_sync(0xffffffffu, a01, off);
                a02 += __shfl_xor_sync(0xffffffffu, a02, off);
                a03 += __shfl_xor_sync(0xffffffffu, a03, off);
                a10 += __shfl_xor_sync(0xffffffffu, a10, off);
                a11 += __shfl_xor_sync(0xffffffffu, a11, off);
                a12 += __shfl_xor_sync(0xffffffffu, a12, off);
                a13 += __shfl_xor_sync(0xffffffffu, a13, off);
            }
        }
        if (lane < 2) {
            float si = (lane == 0) ? a00 : a10;
            float sf = (lane == 0) ? a01 : a11;
            float sg = (lane == 0) ? a02 : a12;
            float so = (lane == 0) ? a03 : a13;
            float xi = z0 + si, xf = z1 + sf, xg = z2 + sg, xo = z3 + so;
            c = sigf(xf) * c + sigf(xi) * tanh_fast(xg);
            float h = sigf(xo) * tanh_fast(c);
            __stcg(&d_hbuf[t & 1][myu], h);
            out[(size_t)t * HH + myu] = h;
            __threadfence();
        }
        grid_barrier((unsigned)(t + 1));
    }
}

// ---------------- launch ----------------
extern "C" void kernel_launch(void* const* d_in, const int* in_sizes, int n_in,
                              void* d_out, int out_size)
{
    const float* input = (const float*)d_in[0];
    const float* gc1_w = (const float*)d_in[3];
    const float* gc1_b = (const float*)d_in[4];
    const float* gc2_w = (const float*)d_in[5];
    const float* gc2_b = (const float*)d_in[6];
    const float* fl_w  = (const float*)d_in[7];
    const float* fl_b  = (const float*)d_in[8];
    const float* il_w  = (const float*)d_in[9];
    const float* il_b  = (const float*)d_in[10];
    const float* ol_w  = (const float*)d_in[11];
    const float* ol_b  = (const float*)d_in[12];
    const float* w_ih  = (const float*)d_in[13];
    const float* w_hh  = (const float*)d_in[14];
    const float* b_ih  = (const float*)d_in[15];
    const float* b_hh  = (const float*)d_in[16];
    float* out = (float*)d_out;

    float* s_xT; cudaGetSymbolAddress((void**)&s_xT, d_xT);
    float* s_fT; cudaGetSymbolAddress((void**)&s_fT, d_fT);
    float* s_iT; cudaGetSymbolAddress((void**)&s_iT, d_iT);
    float* s_zT; cudaGetSymbolAddress((void**)&s_zT, d_zT);
    float* s_Zg; cudaGetSymbolAddress((void**)&s_Zg, d_Zg);

    // idempotent, capture-legal (no stream op, no allocation); no static guard
    cudaFuncSetAttribute(lstm_kernel,
                         cudaFuncAttributeMaxDynamicSharedMemorySize, SMEM_TOTAL);

    gcn_all<<<BATCH, 1024>>>(input, gc1_w, gc1_b, gc2_w, gc2_b, s_xT);

    gemvT<true><<<H16 / 4, 256>>>(s_xT, fl_w, fl_b, s_fT, NPTS, H16);    // relu(f)
    gemvT<true><<<H64 / 4, 256>>>(s_fT, il_w, il_b, s_iT, H16, H64);     // relu(i)
    gemvT<true><<<HH  / 4, 256>>>(s_iT, ol_w, ol_b, s_zT, H64, HH);      // z
    sgemmAT<<<G4 / 64, 256>>>(s_zT, w_ih, b_ih, b_hh, s_Zg, HH, G4);     // Zg

    lstm_kernel<<<NBLK, 256, SMEM_TOTAL>>>(w_hh, out);
}